// round 4
// baseline (speedup 1.0000x reference)
#include <cuda_runtime.h>

// ---------------- static problem geometry ----------------
#define BZ        8
#define MAXLEN    5500
#define NFT       900
// seg0: txt [0,225)     img [225,2025)
// seg1: txt [2025,2250) img [2250,4050)
// pad  [4050,5500)
// attention blocks: [0,2025) and [2025,4050); identical for all 8 batches

// output layout (flattened float32 concat of the 6-tuple)
#define OFF_LOSS   0LL
#define OFF_TOKENS 8LL
#define OFF_TXT    2816008LL
#define OFF_IMG    2860008LL
#define OFF_POS    2904008LL
#define OFF_ATTN   3036008LL

#define ROW_F4        1375u       // 5500/4 float4s per mask row
#define BATCH_F4      7562500u    // 5500*1375 float4s per batch's mask
#define ATTN_ROWS     5500u       // one block per row
#define TOK_BLOCKS    11000u      // 8*5500*64 / 256
#define BLOCKS_PER_B  1375u       // token blocks per batch item

// per-block loss partials + per-batch completion counters.
// g_count wraps back to 0 every call (atomicInc limit) -> graph-replay safe.
__device__ float    g_partials[TOK_BLOCKS];
__device__ unsigned g_count[BZ];

// ---------------- fused kernel ----------------
__global__ void __launch_bounds__(256) k_fused(
        const float* __restrict__ inp,    // [32,16,60,60]
        const float* __restrict__ noise,  // [8,5500,64]
        const float* __restrict__ alphas, // [8]
        float* __restrict__ out) {

    if (blockIdx.x < ATTN_ROWS) {
        // ---------- attention mask: one block per row, replicate to 8 batches ----------
        const unsigned row = blockIdx.x;

        unsigned lo, len;
        if (row < 2025u)      { lo = 0u;    len = 2025u; }
        else if (row < 4050u) { lo = 2025u; len = 2025u; }
        else                  { lo = 0u;    len = 0u;    }

        // compute this thread's 6 float4 values ONCE into registers
        float4 v[6];
        unsigned active = 0;               // bitmask of valid u slots
#pragma unroll
        for (int u = 0; u < 6; u++) {
            const unsigned i = threadIdx.x + u * 256u;   // float4 index in row
            if (i < ROW_F4) {
                active |= 1u << u;
                const unsigned c0 = i * 4u;
                v[u].x = ((c0     - lo) < len) ? 1.0f : 0.0f;
                v[u].y = ((c0 + 1u - lo) < len) ? 1.0f : 0.0f;
                v[u].z = ((c0 + 2u - lo) < len) ? 1.0f : 0.0f;
                v[u].w = ((c0 + 3u - lo) < len) ? 1.0f : 0.0f;
            }
        }

        // store to all 8 batches (row stride ROW_F4, batch stride BATCH_F4)
        float4* __restrict__ dst0 =
            reinterpret_cast<float4*>(out + OFF_ATTN) + (size_t)row * ROW_F4 + threadIdx.x;
#pragma unroll
        for (int b = 0; b < BZ; b++) {
            float4* __restrict__ dst = dst0 + (size_t)b * BATCH_F4;
#pragma unroll
            for (int u = 0; u < 6; u++) {
                if (active & (1u << u)) __stcs(dst + u * 256u, v[u]);
            }
        }
        return;
    }

    // ---------- tokens + masks + position_ids + loss partial ----------
    const unsigned tb  = blockIdx.x - ATTN_ROWS;            // 0 .. 10999
    const unsigned idx = tb * 256u + threadIdx.x;           // < 2,816,000
    const int d  = idx & 63;
    const int bl = idx >> 6;              // b*5500 + L
    const int b  = bl / MAXLEN;
    const int L  = bl - b * MAXLEN;

    const bool img = (L >= 225 && L < 2025) || (L >= 2250 && L < 4050);
    const bool txt = (L < 225) || (L >= 2025 && L < 2250);

    float val = 0.0f;
    float contrib = 0.0f;

    if (img) {
        const int o   = L - 225 - ((L >= 2250) ? 225 : 0);  // [0,3600)
        const int t   = b * 4 + o / NFT;          // global latent frame
        const int rem = o % NFT;
        const int hh  = rem / 30;
        const int ww  = rem - hh * 30;
        const int p = d >> 5, q = (d >> 4) & 1, c = d & 15;
        val = inp[((t * 16 + c) * 60 + (hh * 2 + p)) * 60 + (ww * 2 + q)];

        const float a  = alphas[b];
        const float om = 1.0f - a * a;            // 1 - a^2
        const float diff = val * (a - 1.0f) + noise[idx] * sqrtf(om);
        contrib = diff * diff / (om * 352000.0f); // weighted mean over 352000 elems
    }

    out[OFF_TOKENS + idx] = val;

    if (d == 0) out[OFF_TXT + bl] = txt ? 1.0f : 0.0f;
    if (d == 1) out[OFF_IMG + bl] = img ? 1.0f : 0.0f;
    if (d >= 2 && d < 5) {
        float pv = -1.0f;
        if (img) {
            const int o = L - 225 - ((L >= 2250) ? 225 : 0);
            const int m = o % 1800;               // local index within segment
            const int fi = m / NFT;
            const int r2 = m - fi * NFT;
            const int fj = r2 / 30;
            const int fk = r2 - fj * 30;
            pv = (d == 2) ? (float)fi : (d == 3) ? (float)fj : (float)fk;
        }
        out[OFF_POS + (long long)bl * 3 + (d - 2)] = pv;
    }

    // block reduction of loss contribution (b is uniform within the block)
    __shared__ float s[256];
    __shared__ bool  s_last;
    s[threadIdx.x] = contrib;
    __syncthreads();
#pragma unroll
    for (int st = 128; st > 0; st >>= 1) {
        if (threadIdx.x < (unsigned)st) s[threadIdx.x] += s[threadIdx.x + st];
        __syncthreads();
    }
    if (threadIdx.x == 0) {
        g_partials[tb] = s[0];
        __threadfence();
        unsigned old = atomicInc(&g_count[b], BLOCKS_PER_B - 1u);
        s_last = (old == BLOCKS_PER_B - 1u);
    }
    __syncthreads();

    if (s_last) {
        // final token block of batch b reduces its 1375 partials (fixed order).
        __threadfence();
        float acc = 0.0f;
        for (unsigned i = threadIdx.x; i < BLOCKS_PER_B; i += 256u)
            acc += __ldcg(&g_partials[b * BLOCKS_PER_B + i]);
        s[threadIdx.x] = acc;
        __syncthreads();
#pragma unroll
        for (int st = 128; st > 0; st >>= 1) {
            if (threadIdx.x < (unsigned)st) s[threadIdx.x] += s[threadIdx.x + st];
            __syncthreads();
        }
        if (threadIdx.x == 0) out[OFF_LOSS + b] = s[0];
    }
}

// ---------------- launch ----------------
extern "C" void kernel_launch(void* const* d_in, const int* in_sizes, int n_in,
                              void* d_out, int out_size) {
    const float* inp    = (const float*)d_in[0];  // [1,32,16,60,60]
    const float* noise  = (const float*)d_in[1];  // [8,5500,64]
    const float* alphas = (const float*)d_in[2];  // [8]
    float* out = (float*)d_out;

    k_fused<<<ATTN_ROWS + TOK_BLOCKS, 256>>>(inp, noise, alphas, out);
}

// round 8
// speedup vs baseline: 1.1133x; 1.1133x over previous
#include <cuda_runtime.h>

// ---------------- static problem geometry ----------------
#define BZ        8
#define MAXLEN    5500
#define NFT       900
// seg0: txt [0,225)     img [225,2025)
// seg1: txt [2025,2250) img [2250,4050)
// pad  [4050,5500)
// attention blocks: [0,2025) and [2025,4050); identical for all 8 batches

// output layout (flattened float32 concat of the 6-tuple)
#define OFF_LOSS   0LL
#define OFF_TOKENS 8LL
#define OFF_TXT    2816008LL
#define OFF_IMG    2860008LL
#define OFF_POS    2904008LL
#define OFF_ATTN   3036008LL

#define ATTN_F4_TOTAL 60500000u   // 8*5500*5500/4
#define ROW_F4        1375u       // 5500/4

#define TOK_BLOCKS    11000u      // 8*5500*64 / 256
#define BLOCKS_PER_B  1375u       // token blocks per batch item
#define ATTN_BLOCKS   236329u     // ceil(60,500,000 / 256)

// per-block loss partials + per-batch completion counters.
// g_count wraps back to 0 every call (atomicInc limit) -> graph-replay safe.
__device__ float    g_partials[TOK_BLOCKS];
__device__ unsigned g_count[BZ];

// ---------------- fused kernel ----------------
__global__ void __launch_bounds__(256) k_fused(
        const float* __restrict__ inp,    // [32,16,60,60]
        const float* __restrict__ noise,  // [8,5500,64]
        const float* __restrict__ alphas, // [8]
        float* __restrict__ out) {

    if (blockIdx.x >= TOK_BLOCKS) {
        // ---------- attention mask: 1 float4 per thread, sequential sweep ----------
        // (empirically the fastest store pattern: R2 measured ~140.6us for this shape)
        const unsigned i4 = (blockIdx.x - TOK_BLOCKS) * 256u + threadIdx.x;
        if (i4 >= ATTN_F4_TOTAL) return;
        const unsigned rowall = i4 / ROW_F4;          // 0 .. 43999
        const unsigned col4   = i4 - rowall * ROW_F4;
        const unsigned row    = rowall % MAXLEN;

        int lo, hi;
        if (row < 2025u)      { lo = 0;    hi = 2025; }
        else if (row < 4050u) { lo = 2025; hi = 4050; }
        else                  { lo = 0;    hi = 0; }

        const int c0 = (int)(col4 * 4u);
        float4 v;
        v.x = (c0     >= lo && c0     < hi) ? 1.0f : 0.0f;
        v.y = (c0 + 1 >= lo && c0 + 1 < hi) ? 1.0f : 0.0f;
        v.z = (c0 + 2 >= lo && c0 + 2 < hi) ? 1.0f : 0.0f;
        v.w = (c0 + 3 >= lo && c0 + 3 < hi) ? 1.0f : 0.0f;

        __stcs(reinterpret_cast<float4*>(out + OFF_ATTN) + i4, v);
        return;
    }

    // ---------- tokens + masks + position_ids + loss partial ----------
    const unsigned tb  = blockIdx.x;                        // 0 .. 10999
    const unsigned idx = tb * 256u + threadIdx.x;           // < 2,816,000
    const int d  = idx & 63;
    const int bl = idx >> 6;              // b*5500 + L
    const int b  = bl / MAXLEN;
    const int L  = bl - b * MAXLEN;

    const bool img = (L >= 225 && L < 2025) || (L >= 2250 && L < 4050);
    const bool txt = (L < 225) || (L >= 2025 && L < 2250);

    float val = 0.0f;
    float contrib = 0.0f;

    if (img) {
        const int o   = L - 225 - ((L >= 2250) ? 225 : 0);  // [0,3600)
        const int t   = b * 4 + o / NFT;          // global latent frame
        const int rem = o % NFT;
        const int hh  = rem / 30;
        const int ww  = rem - hh * 30;
        const int p = d >> 5, q = (d >> 4) & 1, c = d & 15;
        val = inp[((t * 16 + c) * 60 + (hh * 2 + p)) * 60 + (ww * 2 + q)];

        const float a  = alphas[b];
        const float om = 1.0f - a * a;            // 1 - a^2
        const float diff = val * (a - 1.0f) + noise[idx] * sqrtf(om);
        contrib = diff * diff / (om * 352000.0f); // weighted mean over 352000 elems
    }

    out[OFF_TOKENS + idx] = val;

    if (d == 0) out[OFF_TXT + bl] = txt ? 1.0f : 0.0f;
    if (d == 1) out[OFF_IMG + bl] = img ? 1.0f : 0.0f;
    if (d >= 2 && d < 5) {
        float pv = -1.0f;
        if (img) {
            const int o = L - 225 - ((L >= 2250) ? 225 : 0);
            const int m = o % 1800;               // local index within segment
            const int fi = m / NFT;
            const int r2 = m - fi * NFT;
            const int fj = r2 / 30;
            const int fk = r2 - fj * 30;
            pv = (d == 2) ? (float)fi : (d == 3) ? (float)fj : (float)fk;
        }
        out[OFF_POS + (long long)bl * 3 + (d - 2)] = pv;
    }

    // block reduction of loss contribution (b is uniform within the block)
    __shared__ float s[256];
    __shared__ bool  s_last;
    s[threadIdx.x] = contrib;
    __syncthreads();
#pragma unroll
    for (int st = 128; st > 0; st >>= 1) {
        if (threadIdx.x < (unsigned)st) s[threadIdx.x] += s[threadIdx.x + st];
        __syncthreads();
    }
    if (threadIdx.x == 0) {
        g_partials[tb] = s[0];
        __threadfence();
        unsigned old = atomicInc(&g_count[b], BLOCKS_PER_B - 1u);
        s_last = (old == BLOCKS_PER_B - 1u);
    }
    __syncthreads();

    if (s_last) {
        // final token block of batch b reduces its 1375 partials (fixed order).
        __threadfence();
        float acc = 0.0f;
        for (unsigned i = threadIdx.x; i < BLOCKS_PER_B; i += 256u)
            acc += __ldcg(&g_partials[b * BLOCKS_PER_B + i]);
        s[threadIdx.x] = acc;
        __syncthreads();
#pragma unroll
        for (int st = 128; st > 0; st >>= 1) {
            if (threadIdx.x < (unsigned)st) s[threadIdx.x] += s[threadIdx.x + st];
            __syncthreads();
        }
        if (threadIdx.x == 0) out[OFF_LOSS + b] = s[0];
    }
}

// ---------------- launch ----------------
extern "C" void kernel_launch(void* const* d_in, const int* in_sizes, int n_in,
                              void* d_out, int out_size) {
    const float* inp    = (const float*)d_in[0];  // [1,32,16,60,60]
    const float* noise  = (const float*)d_in[1];  // [8,5500,64]
    const float* alphas = (const float*)d_in[2];  // [8]
    float* out = (float*)d_out;

    k_fused<<<TOK_BLOCKS + ATTN_BLOCKS, 256>>>(inp, noise, alphas, out);
}